// round 2
// baseline (speedup 1.0000x reference)
#include <cuda_runtime.h>
#include <math.h>

#define NN 50000        // num nodes
#define DD 128          // embedding dim (= hidden dim)
#define BB 4            // num bases
#define EE 320000       // num edges
#define BH 512          // BB * DD  (concatenated bases output width)

// ---------------- static scratch (no runtime allocation allowed) ----------------
__device__ float  g_x[NN * DD];          // node features (ping buffer), 25.6 MB
__device__ float  g_hb[NN * BH];         // per-base projections, 102.4 MB
__device__ float  g_agg[NN * DD];        // scatter accumulator, 25.6 MB
__device__ float  g_inv_deg[NN];
__device__ int    g_deg[NN];
__device__ float  g_W[DD * BH];          // repacked bases [k][b*128+o]
__device__ double g_acc[3];              // loss_pos, loss_neg, auc_count

// ---------------- degree ----------------
__global__ void k_zero_deg() {
    int i = blockIdx.x * blockDim.x + threadIdx.x;
    if (i < NN) g_deg[i] = 0;
}
__global__ void k_count_deg(const int* __restrict__ dst) {
    int e = blockIdx.x * blockDim.x + threadIdx.x;
    if (e < EE) atomicAdd(&g_deg[dst[e]], 1);
}
__global__ void k_inv_deg() {
    int i = blockIdx.x * blockDim.x + threadIdx.x;
    if (i < NN) g_inv_deg[i] = 1.0f / fmaxf((float)g_deg[i], 1.0f);
}

// ---------------- x0 = relu(emb + bias), zero agg ----------------
__global__ void k_x0(const float* __restrict__ emb, const float* __restrict__ eb) {
    int i = blockIdx.x * blockDim.x + threadIdx.x;
    if (i < NN * DD) {
        float v = emb[i] + eb[i & (DD - 1)];
        g_x[i] = v > 0.f ? v : 0.f;
        g_agg[i] = 0.f;
    }
}

// ---------------- repack bases [B,128,128] -> W [128, 512] (col = b*128+o) ----------------
__global__ void k_repack(const float* __restrict__ bases) {
    int i = blockIdx.x * blockDim.x + threadIdx.x;
    if (i < DD * BH) {
        int row = i >> 9;          // k
        int col = i & 511;         // b*128 + o
        int b = col >> 7, o = col & 127;
        g_W[i] = bases[(b * DD + row) * DD + o];
    }
}

// ---------------- GEMM: g_hb[N,512] = g_x[N,128] @ g_W[128,512] ----------------
__global__ __launch_bounds__(256) void k_gemm() {
    __shared__ float As[32][64];   // [k][m]
    __shared__ float Ws[32][64];   // [k][n]
    int bn = blockIdx.x * 64;
    int bm = blockIdx.y * 64;
    int tid = threadIdx.x;
    int tx = tid & 15, ty = tid >> 4;

    float acc[4][4];
#pragma unroll
    for (int i = 0; i < 4; i++)
#pragma unroll
        for (int j = 0; j < 4; j++) acc[i][j] = 0.f;

    for (int kk = 0; kk < DD; kk += 32) {
#pragma unroll
        for (int it = 0; it < 2; it++) {
            int idx = tid + 256 * it;          // 0..511
            int r = idx >> 3, c4 = idx & 7;    // 64 rows x 8 float4-cols
            int grow = bm + r;
            float4 a = make_float4(0.f, 0.f, 0.f, 0.f);
            if (grow < NN) a = *(const float4*)&g_x[grow * DD + kk + c4 * 4];
            As[c4 * 4 + 0][r] = a.x;
            As[c4 * 4 + 1][r] = a.y;
            As[c4 * 4 + 2][r] = a.z;
            As[c4 * 4 + 3][r] = a.w;
        }
#pragma unroll
        for (int it = 0; it < 2; it++) {
            int idx = tid + 256 * it;          // 0..511
            int r = idx >> 4, c4 = idx & 15;   // 32 rows x 16 float4-cols
            *(float4*)&Ws[r][c4 * 4] = *(const float4*)&g_W[(kk + r) * BH + bn + c4 * 4];
        }
        __syncthreads();
#pragma unroll
        for (int k = 0; k < 32; k++) {
            float4 av = *(const float4*)&As[k][ty * 4];
            float4 bv = *(const float4*)&Ws[k][tx * 4];
            acc[0][0] += av.x * bv.x; acc[0][1] += av.x * bv.y; acc[0][2] += av.x * bv.z; acc[0][3] += av.x * bv.w;
            acc[1][0] += av.y * bv.x; acc[1][1] += av.y * bv.y; acc[1][2] += av.y * bv.z; acc[1][3] += av.y * bv.w;
            acc[2][0] += av.z * bv.x; acc[2][1] += av.z * bv.y; acc[2][2] += av.z * bv.z; acc[2][3] += av.z * bv.w;
            acc[3][0] += av.w * bv.x; acc[3][1] += av.w * bv.y; acc[3][2] += av.w * bv.z; acc[3][3] += av.w * bv.w;
        }
        __syncthreads();
    }
#pragma unroll
    for (int i = 0; i < 4; i++) {
        int grow = bm + ty * 4 + i;
        if (grow < NN) {
            float4 o = make_float4(acc[i][0], acc[i][1], acc[i][2], acc[i][3]);
            *(float4*)&g_hb[grow * BH + bn + tx * 4] = o;
        }
    }
}

// ---------------- per-edge message + scatter-add: one warp per edge ----------------
__global__ __launch_bounds__(256) void k_scatter(const int* __restrict__ src,
                                                 const int* __restrict__ dst,
                                                 const int* __restrict__ et,
                                                 const float* __restrict__ comp) {
    int w = (blockIdx.x * blockDim.x + threadIdx.x) >> 5;
    int lane = threadIdx.x & 31;
    if (w >= EE) return;
    int s = src[w], d = dst[w], t = et[w];
    float c0 = __ldg(&comp[t * BB + 0]);
    float c1 = __ldg(&comp[t * BB + 1]);
    float c2 = __ldg(&comp[t * BB + 2]);
    float c3 = __ldg(&comp[t * BB + 3]);
    const float4* hb = (const float4*)&g_hb[s * BH];
    float4 v0 = hb[lane];
    float4 v1 = hb[32 + lane];
    float4 v2 = hb[64 + lane];
    float4 v3 = hb[96 + lane];
    float4 m;
    m.x = c0 * v0.x + c1 * v1.x + c2 * v2.x + c3 * v3.x;
    m.y = c0 * v0.y + c1 * v1.y + c2 * v2.y + c3 * v3.y;
    m.z = c0 * v0.z + c1 * v1.z + c2 * v2.z + c3 * v3.z;
    m.w = c0 * v0.w + c1 * v1.w + c2 * v2.w + c3 * v3.w;
    float* p = &g_agg[d * DD + lane * 4];
    atomicAdd(p + 0, m.x);
    atomicAdd(p + 1, m.y);
    atomicAdd(p + 2, m.z);
    atomicAdd(p + 3, m.w);
}

// ---------------- x = [relu](agg * inv_deg + bias), reset agg ----------------
__global__ void k_finish(const float* __restrict__ bias, int do_relu) {
    int i = blockIdx.x * blockDim.x + threadIdx.x;
    if (i < NN * DD) {
        int n = i >> 7;
        float v = g_agg[i] * g_inv_deg[n] + bias[i & 127];
        if (do_relu) v = fmaxf(v, 0.f);
        g_x[i] = v;
        g_agg[i] = 0.f;
    }
}

// ---------------- decode ----------------
__global__ void k_zero_acc() {
    int i = threadIdx.x;
    if (i < 3) g_acc[i] = 0.0;
}

__device__ __forceinline__ float softplusf(float x) {
    // log(1 + exp(x)), numerically stable
    return fmaxf(x, 0.f) + log1pf(expf(-fabsf(x)));
}

__global__ __launch_bounds__(256) void k_decode(const int* __restrict__ hh,
                                                const int* __restrict__ tt,
                                                const int* __restrict__ et,
                                                const int* __restrict__ ng,
                                                const float* __restrict__ rel,
                                                float* __restrict__ out) {
    __shared__ float s_lp[8], s_ln[8], s_au[8];
    int w = (blockIdx.x * blockDim.x + threadIdx.x) >> 5;
    int lane = threadIdx.x & 31;
    int wid = threadIdx.x >> 5;
    float lp = 0.f, ln = 0.f, au = 0.f;
    if (w < EE) {
        int a = hh[w], b = tt[w], c = ng[w], r = et[w];
        float4 xh = *(const float4*)&g_x[a * DD + lane * 4];
        float4 xt = *(const float4*)&g_x[b * DD + lane * 4];
        float4 xn = *(const float4*)&g_x[c * DD + lane * 4];
        float4 re = *(const float4*)&rel[r * DD + lane * 4];
        float hx = xh.x * re.x, hy = xh.y * re.y, hz = xh.z * re.z, hw = xh.w * re.w;
        float p = hx * xt.x + hy * xt.y + hz * xt.z + hw * xt.w;
        float q = hx * xn.x + hy * xn.y + hz * xn.z + hw * xn.w;
#pragma unroll
        for (int o = 16; o; o >>= 1) {
            p += __shfl_xor_sync(0xFFFFFFFFu, p, o);
            q += __shfl_xor_sync(0xFFFFFFFFu, q, o);
        }
        if (lane == 0) {
            out[w] = p;
            lp = softplusf(-p);   // -log_sigmoid(p)
            ln = softplusf(q);    // -log_sigmoid(-q)
            au = (p > q) ? 1.f : 0.f;
        }
    }
    if (lane == 0) { s_lp[wid] = lp; s_ln[wid] = ln; s_au[wid] = au; }
    __syncthreads();
    if (threadIdx.x == 0) {
        double A = 0, Bd = 0, C = 0;
#pragma unroll
        for (int k = 0; k < 8; k++) { A += s_lp[k]; Bd += s_ln[k]; C += s_au[k]; }
        atomicAdd(&g_acc[0], A);
        atomicAdd(&g_acc[1], Bd);
        atomicAdd(&g_acc[2], C);
    }
}

__global__ void k_final(float* __restrict__ out, int out_size) {
    if (blockIdx.x == 0 && threadIdx.x == 0) {
        double inv = 1.0 / (double)EE;
        if (out_size >= EE + 1) out[EE] = (float)(0.5 * (g_acc[0] + g_acc[1]) * inv);
        if (out_size >= EE + 2) out[EE + 1] = (float)(g_acc[2] * inv);
    }
}

// ---------------- launch ----------------
extern "C" void kernel_launch(void* const* d_in, const int* in_sizes, int n_in,
                              void* d_out, int out_size) {
    const float* emb    = (const float*)d_in[0];   // [N,128]
    const float* ebias  = (const float*)d_in[1];   // [1,128]
    const float* bases1 = (const float*)d_in[2];   // [4,128,128]
    const float* comp1  = (const float*)d_in[3];   // [25,4]
    const float* bias1  = (const float*)d_in[4];   // [128]
    const float* bases2 = (const float*)d_in[5];   // [4,128,128]
    const float* comp2  = (const float*)d_in[6];   // [25,4]
    const float* bias2  = (const float*)d_in[7];   // [128]
    const float* rel    = (const float*)d_in[8];   // [12,128]
    const int*   eidx   = (const int*)d_in[9];     // [2,E]
    const int*   etype  = (const int*)d_in[10];    // [E]
    const int*   negt   = (const int*)d_in[11];    // [E]
    const int* src = eidx;
    const int* dst = eidx + EE;
    float* out = (float*)d_out;

    // degree (shared by both layers)
    k_zero_deg<<<(NN + 255) / 256, 256>>>();
    k_count_deg<<<(EE + 255) / 256, 256>>>(dst);
    k_inv_deg<<<(NN + 255) / 256, 256>>>();

    // x0 = relu(emb + bias); agg = 0
    k_x0<<<(NN * DD + 255) / 256, 256>>>(emb, ebias);

    dim3 ggrid(BH / 64, (NN + 63) / 64);

    // ---- layer 1 ----
    k_repack<<<(DD * BH + 255) / 256, 256>>>(bases1);
    k_gemm<<<ggrid, 256>>>();
    k_scatter<<<EE / 8, 256>>>(src, dst, etype, comp1);
    k_finish<<<(NN * DD + 255) / 256, 256>>>(bias1, 1);

    // ---- layer 2 ----
    k_repack<<<(DD * BH + 255) / 256, 256>>>(bases2);
    k_gemm<<<ggrid, 256>>>();
    k_scatter<<<EE / 8, 256>>>(src, dst, etype, comp2);
    k_finish<<<(NN * DD + 255) / 256, 256>>>(bias2, 0);

    // ---- decode ----
    k_zero_acc<<<1, 32>>>();
    k_decode<<<EE / 8, 256>>>(src, dst, etype, negt, rel, out);
    k_final<<<1, 32>>>(out, out_size);
}

// round 4
// speedup vs baseline: 1.4826x; 1.4826x over previous
#include <cuda_runtime.h>
#include <math.h>

#define NN 50000        // num nodes
#define DD 128          // embedding dim (= hidden dim)
#define BB 4            // num bases
#define EE 320000       // num edges
#define BH 512          // BB * DD  (concatenated bases output width)

// ---------------- static scratch (no runtime allocation allowed) ----------------
__device__ float  g_x[NN * DD];          // node features, 25.6 MB
__device__ float  g_hb[NN * BH];         // per-base projections, 102.4 MB
__device__ float  g_agg[NN * DD];        // scatter accumulator, 25.6 MB
__device__ float  g_inv_deg[NN];
__device__ int    g_deg[NN];
__device__ float  g_W[DD * BH];          // repacked bases [k][b*128+o]
__device__ double g_acc[3];              // loss_pos, loss_neg, auc_count

// ---------------- degree ----------------
__global__ void k_zero_deg() {
    int i = blockIdx.x * blockDim.x + threadIdx.x;
    if (i < NN) g_deg[i] = 0;
}
__global__ void k_count_deg(const int* __restrict__ dst) {
    int e = blockIdx.x * blockDim.x + threadIdx.x;
    if (e < EE) atomicAdd(&g_deg[dst[e]], 1);
}
__global__ void k_inv_deg() {
    int i = blockIdx.x * blockDim.x + threadIdx.x;
    if (i < NN) g_inv_deg[i] = 1.0f / fmaxf((float)g_deg[i], 1.0f);
}

// ---------------- x0 = relu(emb + bias), zero agg ----------------
__global__ void k_x0(const float* __restrict__ emb, const float* __restrict__ eb) {
    int i = blockIdx.x * blockDim.x + threadIdx.x;
    if (i < NN * DD) {
        float v = emb[i] + eb[i & (DD - 1)];
        g_x[i] = v > 0.f ? v : 0.f;
        g_agg[i] = 0.f;
    }
}

// ---------------- repack bases [B,128,128] -> W [128, 512] (col = b*128+o) ----------------
__global__ void k_repack(const float* __restrict__ bases) {
    int i = blockIdx.x * blockDim.x + threadIdx.x;
    if (i < DD * BH) {
        int row = i >> 9;          // k
        int col = i & 511;         // b*128 + o
        int b = col >> 7, o = col & 127;
        g_W[i] = bases[(b * DD + row) * DD + o];
    }
}

// ---------------- tf32 helpers ----------------
__device__ __forceinline__ unsigned f2tf32(float f) {
    unsigned u;
    asm("cvt.rna.tf32.f32 %0, %1;" : "=r"(u) : "f"(f));
    return u;
}
__device__ __forceinline__ void mma_tf32(float c[4], const unsigned a[4], const unsigned b[2]) {
    asm volatile(
        "mma.sync.aligned.m16n8k8.row.col.f32.tf32.tf32.f32 "
        "{%0,%1,%2,%3}, {%4,%5,%6,%7}, {%8,%9}, {%0,%1,%2,%3};\n"
        : "+f"(c[0]), "+f"(c[1]), "+f"(c[2]), "+f"(c[3])
        : "r"(a[0]), "r"(a[1]), "r"(a[2]), "r"(a[3]), "r"(b[0]), "r"(b[1]));
}

// ---------------- tensor-core GEMM: g_hb[N,512] = g_x[N,128] @ g_W[128,512] (tf32) ----------------
// Block tile 128(M) x 128(N) x 32(K). 8 warps: 4 along M x 2 along N -> warp tile 32x64.
__global__ __launch_bounds__(256, 2) void k_gemm_mma() {
    __shared__ unsigned Xs[128][36];   // [m][k], pad->conflict-free A reads
    __shared__ unsigned Ws[32][136];   // [k][n], pad 136 -> bank = 8*tig+gid, conflict-free

    const int bn = blockIdx.x * 128;
    const int bm = blockIdx.y * 128;
    const int tid = threadIdx.x;
    const int lane = tid & 31;
    const int wid = tid >> 5;
    const int wm = wid & 3;            // warp row (0..3), 32 rows each
    const int wn = wid >> 2;           // warp col (0..1), 64 cols each
    const int gid = lane >> 2;         // 0..7
    const int tig = lane & 3;          // 0..3

    float c[2][8][4];
#pragma unroll
    for (int mt = 0; mt < 2; mt++)
#pragma unroll
        for (int nt = 0; nt < 8; nt++)
#pragma unroll
            for (int i = 0; i < 4; i++) c[mt][nt][i] = 0.f;

#pragma unroll
    for (int kc = 0; kc < 4; kc++) {
        // ---- load X tile 128x32 (convert to tf32 at store) ----
#pragma unroll
        for (int it = 0; it < 4; it++) {
            int idx = it * 256 + tid;      // 0..1023 float4s
            int r = idx >> 3, c4 = idx & 7;
            float4 a = make_float4(0.f, 0.f, 0.f, 0.f);
            int grow = bm + r;
            if (grow < NN) a = *(const float4*)&g_x[grow * DD + kc * 32 + c4 * 4];
            uint4 u;
            u.x = f2tf32(a.x); u.y = f2tf32(a.y); u.z = f2tf32(a.z); u.w = f2tf32(a.w);
            *(uint4*)&Xs[r][c4 * 4] = u;
        }
        // ---- load W tile 32x128 ----
#pragma unroll
        for (int it = 0; it < 4; it++) {
            int idx = it * 256 + tid;      // 0..1023 float4s
            int r = idx >> 5, c4 = idx & 31;
            float4 a = *(const float4*)&g_W[(kc * 32 + r) * BH + bn + c4 * 4];
            uint4 u;
            u.x = f2tf32(a.x); u.y = f2tf32(a.y); u.z = f2tf32(a.z); u.w = f2tf32(a.w);
            *(uint4*)&Ws[r][c4 * 4] = u;
        }
        __syncthreads();

#pragma unroll
        for (int ks = 0; ks < 4; ks++) {
            const int k0 = ks * 8 + tig;
            const int k1 = k0 + 4;
            unsigned a[2][4], b[8][2];
#pragma unroll
            for (int mt = 0; mt < 2; mt++) {
                int mr = wm * 32 + mt * 16 + gid;
                a[mt][0] = Xs[mr][k0];
                a[mt][1] = Xs[mr + 8][k0];
                a[mt][2] = Xs[mr][k1];
                a[mt][3] = Xs[mr + 8][k1];
            }
#pragma unroll
            for (int nt = 0; nt < 8; nt++) {
                int nc = wn * 64 + nt * 8 + gid;
                b[nt][0] = Ws[k0][nc];
                b[nt][1] = Ws[k1][nc];
            }
#pragma unroll
            for (int mt = 0; mt < 2; mt++)
#pragma unroll
                for (int nt = 0; nt < 8; nt++)
                    mma_tf32(c[mt][nt], a[mt], b[nt]);
        }
        __syncthreads();
    }

    // ---- store C: each thread owns (2 rows) x (2 cols) per tile ----
#pragma unroll
    for (int mt = 0; mt < 2; mt++) {
        int row0 = bm + wm * 32 + mt * 16 + gid;
        int row1 = row0 + 8;
#pragma unroll
        for (int nt = 0; nt < 8; nt++) {
            int col = bn + wn * 64 + nt * 8 + 2 * tig;
            if (row0 < NN) *(float2*)&g_hb[row0 * BH + col] = make_float2(c[mt][nt][0], c[mt][nt][1]);
            if (row1 < NN) *(float2*)&g_hb[row1 * BH + col] = make_float2(c[mt][nt][2], c[mt][nt][3]);
        }
    }
}

// ---------------- per-edge message + scatter-add: one warp per edge ----------------
__global__ __launch_bounds__(256) void k_scatter(const int* __restrict__ src,
                                                 const int* __restrict__ dst,
                                                 const int* __restrict__ et,
                                                 const float* __restrict__ comp) {
    int w = (blockIdx.x * blockDim.x + threadIdx.x) >> 5;
    int lane = threadIdx.x & 31;
    if (w >= EE) return;
    int s = src[w], d = dst[w], t = et[w];
    float c0 = __ldg(&comp[t * BB + 0]);
    float c1 = __ldg(&comp[t * BB + 1]);
    float c2 = __ldg(&comp[t * BB + 2]);
    float c3 = __ldg(&comp[t * BB + 3]);
    const float4* hb = (const float4*)&g_hb[s * BH];
    float4 v0 = hb[lane];
    float4 v1 = hb[32 + lane];
    float4 v2 = hb[64 + lane];
    float4 v3 = hb[96 + lane];
    float4 m;
    m.x = c0 * v0.x + c1 * v1.x + c2 * v2.x + c3 * v3.x;
    m.y = c0 * v0.y + c1 * v1.y + c2 * v2.y + c3 * v3.y;
    m.z = c0 * v0.z + c1 * v1.z + c2 * v2.z + c3 * v3.z;
    m.w = c0 * v0.w + c1 * v1.w + c2 * v2.w + c3 * v3.w;
    float* p = &g_agg[d * DD + lane * 4];
    atomicAdd(p + 0, m.x);
    atomicAdd(p + 1, m.y);
    atomicAdd(p + 2, m.z);
    atomicAdd(p + 3, m.w);
}

// ---------------- x = [relu](agg * inv_deg + bias), reset agg ----------------
__global__ void k_finish(const float* __restrict__ bias, int do_relu) {
    int i = blockIdx.x * blockDim.x + threadIdx.x;
    if (i < NN * DD) {
        int n = i >> 7;
        float v = g_agg[i] * g_inv_deg[n] + bias[i & 127];
        if (do_relu) v = fmaxf(v, 0.f);
        g_x[i] = v;
        g_agg[i] = 0.f;
    }
}

// ---------------- decode ----------------
__global__ void k_zero_acc() {
    int i = threadIdx.x;
    if (i < 3) g_acc[i] = 0.0;
}

__device__ __forceinline__ float softplusf(float x) {
    return fmaxf(x, 0.f) + log1pf(expf(-fabsf(x)));
}

__global__ __launch_bounds__(256) void k_decode(const int* __restrict__ hh,
                                                const int* __restrict__ tt,
                                                const int* __restrict__ et,
                                                const int* __restrict__ ng,
                                                const float* __restrict__ rel,
                                                float* __restrict__ out) {
    __shared__ float s_lp[8], s_ln[8], s_au[8];
    int w = (blockIdx.x * blockDim.x + threadIdx.x) >> 5;
    int lane = threadIdx.x & 31;
    int wid = threadIdx.x >> 5;
    float lp = 0.f, ln = 0.f, au = 0.f;
    if (w < EE) {
        int a = hh[w], b = tt[w], c = ng[w], r = et[w];
        float4 xh = *(const float4*)&g_x[a * DD + lane * 4];
        float4 xt = *(const float4*)&g_x[b * DD + lane * 4];
        float4 xn = *(const float4*)&g_x[c * DD + lane * 4];
        float4 re = *(const float4*)&rel[r * DD + lane * 4];
        float hx = xh.x * re.x, hy = xh.y * re.y, hz = xh.z * re.z, hw = xh.w * re.w;
        float p = hx * xt.x + hy * xt.y + hz * xt.z + hw * xt.w;
        float q = hx * xn.x + hy * xn.y + hz * xn.z + hw * xn.w;
#pragma unroll
        for (int o = 16; o; o >>= 1) {
            p += __shfl_xor_sync(0xFFFFFFFFu, p, o);
            q += __shfl_xor_sync(0xFFFFFFFFu, q, o);
        }
        if (lane == 0) {
            out[w] = p;
            lp = softplusf(-p);
            ln = softplusf(q);
            au = (p > q) ? 1.f : 0.f;
        }
    }
    if (lane == 0) { s_lp[wid] = lp; s_ln[wid] = ln; s_au[wid] = au; }
    __syncthreads();
    if (threadIdx.x == 0) {
        double A = 0, Bd = 0, C = 0;
#pragma unroll
        for (int k = 0; k < 8; k++) { A += s_lp[k]; Bd += s_ln[k]; C += s_au[k]; }
        atomicAdd(&g_acc[0], A);
        atomicAdd(&g_acc[1], Bd);
        atomicAdd(&g_acc[2], C);
    }
}

__global__ void k_final(float* __restrict__ out, int out_size) {
    if (blockIdx.x == 0 && threadIdx.x == 0) {
        double inv = 1.0 / (double)EE;
        if (out_size >= EE + 1) out[EE] = (float)(0.5 * (g_acc[0] + g_acc[1]) * inv);
        if (out_size >= EE + 2) out[EE + 1] = (float)(g_acc[2] * inv);
    }
}

// ---------------- launch ----------------
extern "C" void kernel_launch(void* const* d_in, const int* in_sizes, int n_in,
                              void* d_out, int out_size) {
    const float* emb    = (const float*)d_in[0];
    const float* ebias  = (const float*)d_in[1];
    const float* bases1 = (const float*)d_in[2];
    const float* comp1  = (const float*)d_in[3];
    const float* bias1  = (const float*)d_in[4];
    const float* bases2 = (const float*)d_in[5];
    const float* comp2  = (const float*)d_in[6];
    const float* bias2  = (const float*)d_in[7];
    const float* rel    = (const float*)d_in[8];
    const int*   eidx   = (const int*)d_in[9];
    const int*   etype  = (const int*)d_in[10];
    const int*   negt   = (const int*)d_in[11];
    const int* src = eidx;
    const int* dst = eidx + EE;
    float* out = (float*)d_out;

    k_zero_deg<<<(NN + 255) / 256, 256>>>();
    k_count_deg<<<(EE + 255) / 256, 256>>>(dst);
    k_inv_deg<<<(NN + 255) / 256, 256>>>();

    k_x0<<<(NN * DD + 255) / 256, 256>>>(emb, ebias);

    dim3 ggrid(BH / 128, (NN + 127) / 128);   // (4, 391)

    // ---- layer 1 ----
    k_repack<<<(DD * BH + 255) / 256, 256>>>(bases1);
    k_gemm_mma<<<ggrid, 256>>>();
    k_scatter<<<EE / 8, 256>>>(src, dst, etype, comp1);
    k_finish<<<(NN * DD + 255) / 256, 256>>>(bias1, 1);

    // ---- layer 2 ----
    k_repack<<<(DD * BH + 255) / 256, 256>>>(bases2);
    k_gemm_mma<<<ggrid, 256>>>();
    k_scatter<<<EE / 8, 256>>>(src, dst, etype, comp2);
    k_finish<<<(NN * DD + 255) / 256, 256>>>(bias2, 0);

    // ---- decode ----
    k_zero_acc<<<1, 32>>>();
    k_decode<<<EE / 8, 256>>>(src, dst, etype, negt, rel, out);
    k_final<<<1, 32>>>(out, out_size);
}

// round 5
// speedup vs baseline: 1.7749x; 1.1972x over previous
#include <cuda_runtime.h>
#include <cuda_fp16.h>
#include <math.h>

#define NN 50000        // num nodes
#define DD 128          // embedding dim (= hidden dim)
#define BB 4            // num bases
#define EE 320000       // num edges
#define BH 512          // BB * DD

// ---------------- static scratch ----------------
__device__ float  g_x[NN * DD];          // node features, 25.6 MB
__device__ __half g_hb_h[NN * BH];       // per-base projections (fp16), 51.2 MB
__device__ float  g_agg[NN * DD];        // scatter accumulator, 25.6 MB
__device__ float  g_inv_deg[NN];
__device__ int    g_deg[NN];
__device__ double g_acc[3];              // loss_pos, loss_neg, auc_count

// ---------------- degree ----------------
__global__ void k_zero_deg() {
    int i = blockIdx.x * blockDim.x + threadIdx.x;
    if (i < NN) g_deg[i] = 0;
}
__global__ void k_count_deg(const int* __restrict__ dst) {
    int e = blockIdx.x * blockDim.x + threadIdx.x;
    if (e < EE) atomicAdd(&g_deg[dst[e]], 1);
}
__global__ void k_inv_deg() {
    int i = blockIdx.x * blockDim.x + threadIdx.x;
    if (i < NN) g_inv_deg[i] = 1.0f / fmaxf((float)g_deg[i], 1.0f);
}

// ---------------- x0 = relu(emb + bias), zero agg ----------------
__global__ void k_x0(const float* __restrict__ emb, const float* __restrict__ eb) {
    int i = blockIdx.x * blockDim.x + threadIdx.x;
    if (i < NN * DD) {
        float v = emb[i] + eb[i & (DD - 1)];
        g_x[i] = v > 0.f ? v : 0.f;
        g_agg[i] = 0.f;
    }
}

// ---------------- tf32 helpers ----------------
__device__ __forceinline__ unsigned f2tf32(float f) {
    unsigned u;
    asm("cvt.rna.tf32.f32 %0, %1;" : "=r"(u) : "f"(f));
    return u;
}
__device__ __forceinline__ void mma_tf32(float c[4], const unsigned a[4], const unsigned b[2]) {
    asm volatile(
        "mma.sync.aligned.m16n8k8.row.col.f32.tf32.tf32.f32 "
        "{%0,%1,%2,%3}, {%4,%5,%6,%7}, {%8,%9}, {%0,%1,%2,%3};\n"
        : "+f"(c[0]), "+f"(c[1]), "+f"(c[2]), "+f"(c[3])
        : "r"(a[0]), "r"(a[1]), "r"(a[2]), "r"(a[3]), "r"(b[0]), "r"(b[1]));
}

// ---------------- split-tf32 GEMM: g_hb_h[N,512] = g_x[N,128] @ W (per-basis) ----------------
// Block tile 128(M) x 128(N) x 16(K). blockIdx.x = basis b (W tile read directly from bases).
// x is split into xhi + xlo (both tf32) -> removes x truncation error.
__global__ __launch_bounds__(256, 2) void k_gemm_mma(const float* __restrict__ bases) {
    __shared__ unsigned Xh[128][20];   // [m][k], pad 20 -> conflict-free a-reads
    __shared__ unsigned Xl[128][20];
    __shared__ unsigned Ws[16][136];   // [k][n], pad 136 -> conflict-free b-reads

    const int b  = blockIdx.x;         // basis index, also N-tile (bn = b*128)
    const int bm = blockIdx.y * 128;
    const int tid = threadIdx.x;
    const int lane = tid & 31;
    const int wid = tid >> 5;
    const int wm = wid & 3;            // warp row (0..3), 32 rows each
    const int wn = wid >> 2;           // warp col (0..1), 64 cols each
    const int gid = lane >> 2;         // 0..7
    const int tig = lane & 3;          // 0..3

    float c[2][8][4];
#pragma unroll
    for (int mt = 0; mt < 2; mt++)
#pragma unroll
        for (int nt = 0; nt < 8; nt++)
#pragma unroll
            for (int i = 0; i < 4; i++) c[mt][nt][i] = 0.f;

#pragma unroll
    for (int kc = 0; kc < 8; kc++) {
        // ---- load X tile 128x16, split hi/lo tf32 ----
#pragma unroll
        for (int it = 0; it < 2; it++) {
            int idx = it * 256 + tid;      // 0..511 float4s
            int r = idx >> 2, c4 = idx & 3;
            float4 a = make_float4(0.f, 0.f, 0.f, 0.f);
            int grow = bm + r;
            if (grow < NN) a = *(const float4*)&g_x[grow * DD + kc * 16 + c4 * 4];
            uint4 hi, lo;
            hi.x = f2tf32(a.x); lo.x = f2tf32(a.x - __uint_as_float(hi.x));
            hi.y = f2tf32(a.y); lo.y = f2tf32(a.y - __uint_as_float(hi.y));
            hi.z = f2tf32(a.z); lo.z = f2tf32(a.z - __uint_as_float(hi.z));
            hi.w = f2tf32(a.w); lo.w = f2tf32(a.w - __uint_as_float(hi.w));
            *(uint4*)&Xh[r][c4 * 4] = hi;
            *(uint4*)&Xl[r][c4 * 4] = lo;
        }
        // ---- load W tile 16x128 directly from bases[b] ----
#pragma unroll
        for (int it = 0; it < 2; it++) {
            int idx = it * 256 + tid;      // 0..511 float4s
            int r = idx >> 5, c4 = idx & 31;
            float4 a = *(const float4*)&bases[(b * DD + kc * 16 + r) * DD + c4 * 4];
            uint4 u;
            u.x = f2tf32(a.x); u.y = f2tf32(a.y); u.z = f2tf32(a.z); u.w = f2tf32(a.w);
            *(uint4*)&Ws[r][c4 * 4] = u;
        }
        __syncthreads();

#pragma unroll
        for (int ks = 0; ks < 2; ks++) {
            const int k0 = ks * 8 + tig;
            const int k1 = k0 + 4;
            unsigned ah[2][4], al[2][4], bf[8][2];
#pragma unroll
            for (int mt = 0; mt < 2; mt++) {
                int mr = wm * 32 + mt * 16 + gid;
                ah[mt][0] = Xh[mr][k0];      al[mt][0] = Xl[mr][k0];
                ah[mt][1] = Xh[mr + 8][k0];  al[mt][1] = Xl[mr + 8][k0];
                ah[mt][2] = Xh[mr][k1];      al[mt][2] = Xl[mr][k1];
                ah[mt][3] = Xh[mr + 8][k1];  al[mt][3] = Xl[mr + 8][k1];
            }
#pragma unroll
            for (int nt = 0; nt < 8; nt++) {
                int nc = wn * 64 + nt * 8 + gid;
                bf[nt][0] = Ws[k0][nc];
                bf[nt][1] = Ws[k1][nc];
            }
#pragma unroll
            for (int mt = 0; mt < 2; mt++)
#pragma unroll
                for (int nt = 0; nt < 8; nt++) {
                    mma_tf32(c[mt][nt], al[mt], bf[nt]);
                    mma_tf32(c[mt][nt], ah[mt], bf[nt]);
                }
        }
        __syncthreads();
    }

    // ---- store C as fp16 ----
#pragma unroll
    for (int mt = 0; mt < 2; mt++) {
        int row0 = bm + wm * 32 + mt * 16 + gid;
        int row1 = row0 + 8;
#pragma unroll
        for (int nt = 0; nt < 8; nt++) {
            int col = b * 128 + wn * 64 + nt * 8 + 2 * tig;
            if (row0 < NN)
                *(__half2*)&g_hb_h[row0 * BH + col] = __floats2half2_rn(c[mt][nt][0], c[mt][nt][1]);
            if (row1 < NN)
                *(__half2*)&g_hb_h[row1 * BH + col] = __floats2half2_rn(c[mt][nt][2], c[mt][nt][3]);
        }
    }
}

// ---------------- per-edge message + scatter-add: one warp per edge ----------------
__global__ __launch_bounds__(256) void k_scatter(const int* __restrict__ src,
                                                 const int* __restrict__ dst,
                                                 const int* __restrict__ et,
                                                 const float* __restrict__ comp) {
    int w = (blockIdx.x * blockDim.x + threadIdx.x) >> 5;
    int lane = threadIdx.x & 31;
    if (w >= EE) return;
    int s = src[w], d = dst[w], t = et[w];
    float cc[4];
    cc[0] = __ldg(&comp[t * BB + 0]);
    cc[1] = __ldg(&comp[t * BB + 1]);
    cc[2] = __ldg(&comp[t * BB + 2]);
    cc[3] = __ldg(&comp[t * BB + 3]);
    const uint2* hb = (const uint2*)&g_hb_h[s * BH];   // 128 uint2 = 512 halves
    float4 m = make_float4(0.f, 0.f, 0.f, 0.f);
#pragma unroll
    for (int bb = 0; bb < 4; bb++) {
        uint2 u = hb[bb * 32 + lane];
        float2 f0 = __half22float2(*(const __half2*)&u.x);
        float2 f1 = __half22float2(*(const __half2*)&u.y);
        m.x = fmaf(cc[bb], f0.x, m.x);
        m.y = fmaf(cc[bb], f0.y, m.y);
        m.z = fmaf(cc[bb], f1.x, m.z);
        m.w = fmaf(cc[bb], f1.y, m.w);
    }
    float* p = &g_agg[d * DD + lane * 4];
    asm volatile("red.global.add.v4.f32 [%0], {%1,%2,%3,%4};"
                 :: "l"(p), "f"(m.x), "f"(m.y), "f"(m.z), "f"(m.w) : "memory");
}

// ---------------- x = [relu](agg * inv_deg + bias), reset agg ----------------
__global__ void k_finish(const float* __restrict__ bias, int do_relu) {
    int i = blockIdx.x * blockDim.x + threadIdx.x;
    if (i < NN * DD) {
        int n = i >> 7;
        float v = g_agg[i] * g_inv_deg[n] + bias[i & 127];
        if (do_relu) v = fmaxf(v, 0.f);
        g_x[i] = v;
        g_agg[i] = 0.f;
    }
}

// ---------------- decode ----------------
__global__ void k_zero_acc() {
    int i = threadIdx.x;
    if (i < 3) g_acc[i] = 0.0;
}

__device__ __forceinline__ float softplusf(float x) {
    return fmaxf(x, 0.f) + log1pf(expf(-fabsf(x)));
}

__global__ __launch_bounds__(256) void k_decode(const int* __restrict__ hh,
                                                const int* __restrict__ tt,
                                                const int* __restrict__ et,
                                                const int* __restrict__ ng,
                                                const float* __restrict__ rel,
                                                float* __restrict__ out) {
    __shared__ float s_lp[8], s_ln[8], s_au[8];
    int w = (blockIdx.x * blockDim.x + threadIdx.x) >> 5;
    int lane = threadIdx.x & 31;
    int wid = threadIdx.x >> 5;
    float lp = 0.f, ln = 0.f, au = 0.f;
    if (w < EE) {
        int a = hh[w], b = tt[w], c = ng[w], r = et[w];
        float4 xh = *(const float4*)&g_x[a * DD + lane * 4];
        float4 xt = *(const float4*)&g_x[b * DD + lane * 4];
        float4 xn = *(const float4*)&g_x[c * DD + lane * 4];
        float4 re = *(const float4*)&rel[r * DD + lane * 4];
        float hx = xh.x * re.x, hy = xh.y * re.y, hz = xh.z * re.z, hw = xh.w * re.w;
        float p = hx * xt.x + hy * xt.y + hz * xt.z + hw * xt.w;
        float q = hx * xn.x + hy * xn.y + hz * xn.z + hw * xn.w;
#pragma unroll
        for (int o = 16; o; o >>= 1) {
            p += __shfl_xor_sync(0xFFFFFFFFu, p, o);
            q += __shfl_xor_sync(0xFFFFFFFFu, q, o);
        }
        if (lane == 0) {
            out[w] = p;
            lp = softplusf(-p);
            ln = softplusf(q);
            au = (p > q) ? 1.f : 0.f;
        }
    }
    if (lane == 0) { s_lp[wid] = lp; s_ln[wid] = ln; s_au[wid] = au; }
    __syncthreads();
    if (threadIdx.x == 0) {
        double A = 0, Bd = 0, C = 0;
#pragma unroll
        for (int k = 0; k < 8; k++) { A += s_lp[k]; Bd += s_ln[k]; C += s_au[k]; }
        atomicAdd(&g_acc[0], A);
        atomicAdd(&g_acc[1], Bd);
        atomicAdd(&g_acc[2], C);
    }
}

__global__ void k_final(float* __restrict__ out, int out_size) {
    if (blockIdx.x == 0 && threadIdx.x == 0) {
        double inv = 1.0 / (double)EE;
        if (out_size >= EE + 1) out[EE] = (float)(0.5 * (g_acc[0] + g_acc[1]) * inv);
        if (out_size >= EE + 2) out[EE + 1] = (float)(g_acc[2] * inv);
    }
}

// ---------------- launch ----------------
extern "C" void kernel_launch(void* const* d_in, const int* in_sizes, int n_in,
                              void* d_out, int out_size) {
    const float* emb    = (const float*)d_in[0];
    const float* ebias  = (const float*)d_in[1];
    const float* bases1 = (const float*)d_in[2];
    const float* comp1  = (const float*)d_in[3];
    const float* bias1  = (const float*)d_in[4];
    const float* bases2 = (const float*)d_in[5];
    const float* comp2  = (const float*)d_in[6];
    const float* bias2  = (const float*)d_in[7];
    const float* rel    = (const float*)d_in[8];
    const int*   eidx   = (const int*)d_in[9];
    const int*   etype  = (const int*)d_in[10];
    const int*   negt   = (const int*)d_in[11];
    const int* src = eidx;
    const int* dst = eidx + EE;
    float* out = (float*)d_out;

    k_zero_deg<<<(NN + 255) / 256, 256>>>();
    k_count_deg<<<(EE + 255) / 256, 256>>>(dst);
    k_inv_deg<<<(NN + 255) / 256, 256>>>();

    k_x0<<<(NN * DD + 255) / 256, 256>>>(emb, ebias);

    dim3 ggrid(BB, (NN + 127) / 128);   // (4, 391); blockIdx.x = basis

    // ---- layer 1 ----
    k_gemm_mma<<<ggrid, 256>>>(bases1);
    k_scatter<<<EE / 8, 256>>>(src, dst, etype, comp1);
    k_finish<<<(NN * DD + 255) / 256, 256>>>(bias1, 1);

    // ---- layer 2 ----
    k_gemm_mma<<<ggrid, 256>>>(bases2);
    k_scatter<<<EE / 8, 256>>>(src, dst, etype, comp2);
    k_finish<<<(NN * DD + 255) / 256, 256>>>(bias2, 0);

    // ---- decode ----
    k_zero_acc<<<1, 32>>>();
    k_decode<<<EE / 8, 256>>>(src, dst, etype, negt, rel, out);
    k_final<<<1, 32>>>(out, out_size);
}

// round 6
// speedup vs baseline: 2.0960x; 1.1809x over previous
#include <cuda_runtime.h>
#include <cuda_fp16.h>
#include <math.h>

#define NN 50000        // num nodes
#define DD 128          // embedding dim (= hidden dim)
#define BB 4            // num bases
#define EE 320000       // num edges
#define BH 512          // BB * DD

// ---------------- static scratch ----------------
__device__ float  g_x[NN * DD];          // node features, 25.6 MB
__device__ __half g_hb_h[NN * BH];       // per-base projections (fp16), 51.2 MB
__device__ float  g_agg[NN * DD];        // scatter accumulator, 25.6 MB
__device__ int    g_deg[NN];
__device__ double g_acc[3];              // loss_pos, loss_neg, auc_count

// ---------------- degree ----------------
__global__ void k_zero_deg() {
    int i = blockIdx.x * blockDim.x + threadIdx.x;
    if (i < NN) g_deg[i] = 0;
}
__global__ void k_count_deg(const int* __restrict__ dst) {
    int e = blockIdx.x * blockDim.x + threadIdx.x;
    if (e < EE) atomicAdd(&g_deg[dst[e]], 1);
}

// ---------------- x0 = relu(emb + bias), zero agg (float4) ----------------
__global__ void k_x0(const float* __restrict__ emb, const float* __restrict__ eb) {
    int i = blockIdx.x * blockDim.x + threadIdx.x;     // float4 index
    if (i < NN * DD / 4) {
        float4 v = *(const float4*)&emb[i * 4];
        float4 bsv = *(const float4*)&eb[(i & 31) * 4];
        v.x = fmaxf(v.x + bsv.x, 0.f);
        v.y = fmaxf(v.y + bsv.y, 0.f);
        v.z = fmaxf(v.z + bsv.z, 0.f);
        v.w = fmaxf(v.w + bsv.w, 0.f);
        *(float4*)&g_x[i * 4] = v;
        *(float4*)&g_agg[i * 4] = make_float4(0.f, 0.f, 0.f, 0.f);
    }
}

// ---------------- tf32 helpers ----------------
__device__ __forceinline__ unsigned f2tf32(float f) {
    unsigned u;
    asm("cvt.rna.tf32.f32 %0, %1;" : "=r"(u) : "f"(f));
    return u;
}
__device__ __forceinline__ void mma_tf32(float c[4], const unsigned a[4], const unsigned b[2]) {
    asm volatile(
        "mma.sync.aligned.m16n8k8.row.col.f32.tf32.tf32.f32 "
        "{%0,%1,%2,%3}, {%4,%5,%6,%7}, {%8,%9}, {%0,%1,%2,%3};\n"
        : "+f"(c[0]), "+f"(c[1]), "+f"(c[2]), "+f"(c[3])
        : "r"(a[0]), "r"(a[1]), "r"(a[2]), "r"(a[3]), "r"(b[0]), "r"(b[1]));
}

// ---------------- tf32 GEMM: g_hb_h[N,512] = g_x[N,128] @ bases[b] (per-basis) ----------------
// Block tile 128(M) x 128(N) x 32(K). blockIdx.x = basis b. fp16 output.
__global__ __launch_bounds__(256, 2) void k_gemm_mma(const float* __restrict__ bases) {
    __shared__ unsigned Xs[128][36];   // [m][k], pad -> conflict-free a-reads
    __shared__ unsigned Ws[32][136];   // [k][n], pad 136 -> conflict-free b-reads

    const int b  = blockIdx.x;         // basis index (N-tile = b*128)
    const int bm = blockIdx.y * 128;
    const int tid = threadIdx.x;
    const int lane = tid & 31;
    const int wid = tid >> 5;
    const int wm = wid & 3;            // warp row (0..3), 32 rows each
    const int wn = wid >> 2;           // warp col (0..1), 64 cols each
    const int gid = lane >> 2;         // 0..7
    const int tig = lane & 3;          // 0..3

    float c[2][8][4];
#pragma unroll
    for (int mt = 0; mt < 2; mt++)
#pragma unroll
        for (int nt = 0; nt < 8; nt++)
#pragma unroll
            for (int i = 0; i < 4; i++) c[mt][nt][i] = 0.f;

#pragma unroll
    for (int kc = 0; kc < 4; kc++) {
        // ---- load X tile 128x32 (tf32 at store) ----
#pragma unroll
        for (int it = 0; it < 4; it++) {
            int idx = it * 256 + tid;      // 0..1023 float4s
            int r = idx >> 3, c4 = idx & 7;
            float4 a = make_float4(0.f, 0.f, 0.f, 0.f);
            int grow = bm + r;
            if (grow < NN) a = *(const float4*)&g_x[grow * DD + kc * 32 + c4 * 4];
            uint4 u;
            u.x = f2tf32(a.x); u.y = f2tf32(a.y); u.z = f2tf32(a.z); u.w = f2tf32(a.w);
            *(uint4*)&Xs[r][c4 * 4] = u;
        }
        // ---- load W tile 32x128 directly from bases[b] ----
#pragma unroll
        for (int it = 0; it < 4; it++) {
            int idx = it * 256 + tid;      // 0..1023 float4s
            int r = idx >> 5, c4 = idx & 31;
            float4 a = *(const float4*)&bases[(b * DD + kc * 32 + r) * DD + c4 * 4];
            uint4 u;
            u.x = f2tf32(a.x); u.y = f2tf32(a.y); u.z = f2tf32(a.z); u.w = f2tf32(a.w);
            *(uint4*)&Ws[r][c4 * 4] = u;
        }
        __syncthreads();

#pragma unroll
        for (int ks = 0; ks < 4; ks++) {
            const int k0 = ks * 8 + tig;
            const int k1 = k0 + 4;
            unsigned a[2][4], bf[8][2];
#pragma unroll
            for (int mt = 0; mt < 2; mt++) {
                int mr = wm * 32 + mt * 16 + gid;
                a[mt][0] = Xs[mr][k0];
                a[mt][1] = Xs[mr + 8][k0];
                a[mt][2] = Xs[mr][k1];
                a[mt][3] = Xs[mr + 8][k1];
            }
#pragma unroll
            for (int nt = 0; nt < 8; nt++) {
                int nc = wn * 64 + nt * 8 + gid;
                bf[nt][0] = Ws[k0][nc];
                bf[nt][1] = Ws[k1][nc];
            }
#pragma unroll
            for (int mt = 0; mt < 2; mt++)
#pragma unroll
                for (int nt = 0; nt < 8; nt++)
                    mma_tf32(c[mt][nt], a[mt], bf[nt]);
        }
        __syncthreads();
    }

    // ---- store C as fp16 ----
#pragma unroll
    for (int mt = 0; mt < 2; mt++) {
        int row0 = bm + wm * 32 + mt * 16 + gid;
        int row1 = row0 + 8;
#pragma unroll
        for (int nt = 0; nt < 8; nt++) {
            int col = b * 128 + wn * 64 + nt * 8 + 2 * tig;
            if (row0 < NN)
                *(__half2*)&g_hb_h[row0 * BH + col] = __floats2half2_rn(c[mt][nt][0], c[mt][nt][1]);
            if (row1 < NN)
                *(__half2*)&g_hb_h[row1 * BH + col] = __floats2half2_rn(c[mt][nt][2], c[mt][nt][3]);
        }
    }
}

// ---------------- per-edge message + scatter-add: one warp per edge ----------------
__global__ __launch_bounds__(256) void k_scatter(const int* __restrict__ src,
                                                 const int* __restrict__ dst,
                                                 const int* __restrict__ et,
                                                 const float* __restrict__ comp) {
    int w = (blockIdx.x * blockDim.x + threadIdx.x) >> 5;
    int lane = threadIdx.x & 31;
    if (w >= EE) return;
    int s = src[w], d = dst[w], t = et[w];
    float cc[4];
    cc[0] = __ldg(&comp[t * BB + 0]);
    cc[1] = __ldg(&comp[t * BB + 1]);
    cc[2] = __ldg(&comp[t * BB + 2]);
    cc[3] = __ldg(&comp[t * BB + 3]);
    const uint2* hb = (const uint2*)&g_hb_h[s * BH];   // 128 uint2 = 512 halves
    float4 m = make_float4(0.f, 0.f, 0.f, 0.f);
#pragma unroll
    for (int bb = 0; bb < 4; bb++) {
        uint2 u = hb[bb * 32 + lane];
        float2 f0 = __half22float2(*(const __half2*)&u.x);
        float2 f1 = __half22float2(*(const __half2*)&u.y);
        m.x = fmaf(cc[bb], f0.x, m.x);
        m.y = fmaf(cc[bb], f0.y, m.y);
        m.z = fmaf(cc[bb], f1.x, m.z);
        m.w = fmaf(cc[bb], f1.y, m.w);
    }
    float* p = &g_agg[d * DD + lane * 4];
    asm volatile("red.global.add.v4.f32 [%0], {%1,%2,%3,%4};"
                 :: "l"(p), "f"(m.x), "f"(m.y), "f"(m.z), "f"(m.w) : "memory");
}

// ---------------- x = [relu](agg / deg + bias), reset agg (float4) ----------------
__global__ void k_finish(const float* __restrict__ bias, int do_relu) {
    int i = blockIdx.x * blockDim.x + threadIdx.x;     // float4 index
    if (i < NN * DD / 4) {
        int n = i >> 5;                                // node = i*4 / 128
        float inv = 1.0f / fmaxf((float)g_deg[n], 1.0f);
        float4 v = *(const float4*)&g_agg[i * 4];
        float4 bsv = *(const float4*)&bias[(i & 31) * 4];
        v.x = v.x * inv + bsv.x;
        v.y = v.y * inv + bsv.y;
        v.z = v.z * inv + bsv.z;
        v.w = v.w * inv + bsv.w;
        if (do_relu) {
            v.x = fmaxf(v.x, 0.f); v.y = fmaxf(v.y, 0.f);
            v.z = fmaxf(v.z, 0.f); v.w = fmaxf(v.w, 0.f);
        }
        *(float4*)&g_x[i * 4] = v;
        *(float4*)&g_agg[i * 4] = make_float4(0.f, 0.f, 0.f, 0.f);
    }
}

// ---------------- decode ----------------
__global__ void k_zero_acc() {
    int i = threadIdx.x;
    if (i < 3) g_acc[i] = 0.0;
}

__device__ __forceinline__ float softplusf(float x) {
    return fmaxf(x, 0.f) + log1pf(expf(-fabsf(x)));
}

__global__ __launch_bounds__(256) void k_decode(const int* __restrict__ hh,
                                                const int* __restrict__ tt,
                                                const int* __restrict__ et,
                                                const int* __restrict__ ng,
                                                const float* __restrict__ rel,
                                                float* __restrict__ out) {
    __shared__ float s_lp[8], s_ln[8], s_au[8];
    int w = (blockIdx.x * blockDim.x + threadIdx.x) >> 5;
    int lane = threadIdx.x & 31;
    int wid = threadIdx.x >> 5;
    float lp = 0.f, ln = 0.f, au = 0.f;
    if (w < EE) {
        int a = hh[w], b = tt[w], c = ng[w], r = et[w];
        float4 xh = *(const float4*)&g_x[a * DD + lane * 4];
        float4 xt = *(const float4*)&g_x[b * DD + lane * 4];
        float4 xn = *(const float4*)&g_x[c * DD + lane * 4];
        float4 re = *(const float4*)&rel[r * DD + lane * 4];
        float hx = xh.x * re.x, hy = xh.y * re.y, hz = xh.z * re.z, hw = xh.w * re.w;
        float p = hx * xt.x + hy * xt.y + hz * xt.z + hw * xt.w;
        float q = hx * xn.x + hy * xn.y + hz * xn.z + hw * xn.w;
#pragma unroll
        for (int o = 16; o; o >>= 1) {
            p += __shfl_xor_sync(0xFFFFFFFFu, p, o);
            q += __shfl_xor_sync(0xFFFFFFFFu, q, o);
        }
        if (lane == 0) {
            out[w] = p;
            lp = softplusf(-p);
            ln = softplusf(q);
            au = (p > q) ? 1.f : 0.f;
        }
    }
    if (lane == 0) { s_lp[wid] = lp; s_ln[wid] = ln; s_au[wid] = au; }
    __syncthreads();
    if (threadIdx.x == 0) {
        double A = 0, Bd = 0, C = 0;
#pragma unroll
        for (int k = 0; k < 8; k++) { A += s_lp[k]; Bd += s_ln[k]; C += s_au[k]; }
        atomicAdd(&g_acc[0], A);
        atomicAdd(&g_acc[1], Bd);
        atomicAdd(&g_acc[2], C);
    }
}

__global__ void k_final(float* __restrict__ out, int out_size) {
    if (blockIdx.x == 0 && threadIdx.x == 0) {
        double inv = 1.0 / (double)EE;
        if (out_size >= EE + 1) out[EE] = (float)(0.5 * (g_acc[0] + g_acc[1]) * inv);
        if (out_size >= EE + 2) out[EE + 1] = (float)(g_acc[2] * inv);
    }
}

// ---------------- launch ----------------
extern "C" void kernel_launch(void* const* d_in, const int* in_sizes, int n_in,
                              void* d_out, int out_size) {
    const float* emb    = (const float*)d_in[0];
    const float* ebias  = (const float*)d_in[1];
    const float* bases1 = (const float*)d_in[2];
    const float* comp1  = (const float*)d_in[3];
    const float* bias1  = (const float*)d_in[4];
    const float* bases2 = (const float*)d_in[5];
    const float* comp2  = (const float*)d_in[6];
    const float* bias2  = (const float*)d_in[7];
    const float* rel    = (const float*)d_in[8];
    const int*   eidx   = (const int*)d_in[9];
    const int*   etype  = (const int*)d_in[10];
    const int*   negt   = (const int*)d_in[11];
    const int* src = eidx;
    const int* dst = eidx + EE;
    float* out = (float*)d_out;

    k_zero_deg<<<(NN + 255) / 256, 256>>>();
    k_count_deg<<<(EE + 255) / 256, 256>>>(dst);

    k_x0<<<(NN * DD / 4 + 255) / 256, 256>>>(emb, ebias);

    dim3 ggrid(BB, (NN + 127) / 128);   // (4, 391); blockIdx.x = basis

    // ---- layer 1 ----
    k_gemm_mma<<<ggrid, 256>>>(bases1);
    k_scatter<<<EE / 8, 256>>>(src, dst, etype, comp1);
    k_finish<<<(NN * DD / 4 + 255) / 256, 256>>>(bias1, 1);

    // ---- layer 2 ----
    k_gemm_mma<<<ggrid, 256>>>(bases2);
    k_scatter<<<EE / 8, 256>>>(src, dst, etype, comp2);
    k_finish<<<(NN * DD / 4 + 255) / 256, 256>>>(bias2, 0);

    // ---- decode ----
    k_zero_acc<<<1, 32>>>();
    k_decode<<<EE / 8, 256>>>(src, dst, etype, negt, rel, out);
    k_final<<<1, 32>>>(out, out_size);
}